// round 1
// baseline (speedup 1.0000x reference)
#include <cuda_runtime.h>

#define B_   2
#define C_   32
#define T_   64
#define HW_  4096
#define N_   512
#define CH_  16
#define FT_  400
#define L_   (FT_*N_)        /* 204800 */
#define CNT_ (B_*L_)         /* 409600 */
#define OUT_OFF_RESULT ((size_t)B_*CH_*L_)  /* 6,553,600 */

// ---- scratch (device globals: allocation-free rule) ----
__device__ float g_Weff[CH_*C_];
__device__ float g_beff[CH_];
__device__ float g_r[B_*T_*HW_];                         // 2 MB
__device__ __align__(16) float g_h[(size_t)B_*N_*FT_*CH_]; // 26 MB, layout [b][n][t][o]
__device__ float g_part[1024*32];                        // per-block partial sums/sumsqs
__device__ float g_scale[CH_];
__device__ float g_shift[CH_];

// Fold W1@Wf -> Weff (16x32), and b1 + W1@bf -> beff
__global__ void k_init(const float* __restrict__ W1, const float* __restrict__ Wf,
                       const float* __restrict__ b1, const float* __restrict__ bf) {
    int t = threadIdx.x;                 // 512 threads
    int o = t >> 5, c = t & 31;
    float a = 0.f;
    #pragma unroll
    for (int k = 0; k < 32; k++) a += W1[o*32+k] * Wf[k*32+c];
    g_Weff[t] = a;
    if (t < CH_) {
        float bb = b1[t];
        #pragma unroll
        for (int k = 0; k < 32; k++) bb += W1[t*32+k] * bf[k];
        g_beff[t] = bb;
    }
}

// r[b][t][hw] = Wr . x[b][:][t][hw] + br   (streams the whole x, 67 MB)
__global__ void k_r(const float* __restrict__ x, const float* __restrict__ Wr,
                    const float* __restrict__ br) {
    __shared__ float w[32];
    if (threadIdx.x < 32) w[threadIdx.x] = Wr[threadIdx.x];
    __syncthreads();
    int tid = blockIdx.x*blockDim.x + threadIdx.x;   // 524288
    int hw = tid & (HW_-1);
    int bt = tid >> 12;
    int b = bt >> 6, t = bt & 63;
    const float* xp = x + (size_t)(b*C_*T_ + t)*HW_ + hw;
    float acc = br[0];
    #pragma unroll
    for (int c = 0; c < 32; c++) acc += w[c] * xp[(size_t)c*T_*HW_];
    g_r[tid] = acc;
}

// result[b][t_out][hw] = lerp_t(r) -> d_out tail
__global__ void k_r2(float* __restrict__ out) {
    int tid = blockIdx.x*blockDim.x + threadIdx.x;   // 3,276,800
    if (tid >= B_*FT_*HW_) return;
    int hw = tid & (HW_-1);
    int bt = tid >> 12;
    int t = bt % FT_;
    int b = bt / FT_;
    const float step = (float)(63.0/399.0);
    float pos = (float)t * step;
    int i0 = (int)pos;
    int i1 = min(i0+1, T_-1);
    float w = pos - (float)i0;
    float v = g_r[(b*T_+i0)*HW_+hw]*(1.f-w) + g_r[(b*T_+i1)*HW_+hw]*w;
    out[OUT_OFF_RESULT + (size_t)tid] = v;
}

// Per (b,n): gather x[.,.,idx] (32x64) -> f = Weff@xg (16x64) -> lerp to 400
// -> write h, accumulate per-channel sum/sumsq partials (deterministic).
__global__ void k_gather(const float* __restrict__ x, const int* __restrict__ coord) {
    __shared__ float xg[C_*T_];      // 2048
    __shared__ float sWe[CH_*C_];    // 512
    __shared__ float sbe[CH_];
    __shared__ float sf[CH_*T_];     // 1024
    __shared__ float red[32*128];    // 4096

    int bn = blockIdx.x;             // 1024 = B*N
    int b = bn >> 9;
    int hcoord = coord[bn*2], wcoord = coord[bn*2+1];
    int idx = hcoord*64 + wcoord;

    const float* xp = x + (size_t)b*C_*T_*HW_ + idx;
    for (int e = threadIdx.x; e < C_*T_; e += 128)
        xg[e] = xp[(size_t)e * HW_];            // e = c*64+t -> offset (c*T+t)*HW
    for (int e = threadIdx.x; e < CH_*C_; e += 128) sWe[e] = g_Weff[e];
    if (threadIdx.x < CH_) sbe[threadIdx.x] = g_beff[threadIdx.x];
    __syncthreads();

    // phase 1: f[o][t] = beff[o] + sum_c Weff[o][c] * xg[c][t]
    for (int e = threadIdx.x; e < CH_*T_; e += 128) {
        int o = e >> 6, t = e & 63;
        float a = sbe[o];
        #pragma unroll
        for (int c = 0; c < 32; c++) a += sWe[o*32+c] * xg[c*64+t];
        sf[e] = a;
    }
    __syncthreads();

    // phase 2: lerp to 400, store h, accumulate stats
    float s[CH_], q[CH_];
    #pragma unroll
    for (int o = 0; o < CH_; o++) { s[o] = 0.f; q[o] = 0.f; }
    const float step = (float)(63.0/399.0);
    for (int t = threadIdx.x; t < FT_; t += 128) {
        float pos = (float)t * step;
        int i0 = (int)pos;
        int i1 = min(i0+1, T_-1);
        float w = pos - (float)i0, w0 = 1.f - w;
        float hv[CH_];
        #pragma unroll
        for (int o = 0; o < CH_; o++) {
            float v = sf[o*64+i0]*w0 + sf[o*64+i1]*w;
            hv[o] = v; s[o] += v; q[o] += v*v;
        }
        float4* dst = (float4*)(g_h + ((size_t)bn*FT_ + t)*CH_);
        dst[0] = make_float4(hv[0],hv[1],hv[2],hv[3]);
        dst[1] = make_float4(hv[4],hv[5],hv[6],hv[7]);
        dst[2] = make_float4(hv[8],hv[9],hv[10],hv[11]);
        dst[3] = make_float4(hv[12],hv[13],hv[14],hv[15]);
    }

    // deterministic block reduction: rows 0..15 sum, 16..31 sumsq
    #pragma unroll
    for (int o = 0; o < CH_; o++) {
        red[o*128 + threadIdx.x]        = s[o];
        red[(CH_+o)*128 + threadIdx.x]  = q[o];
    }
    __syncthreads();
    if (threadIdx.x < 32) {
        float tot = 0.f;
        #pragma unroll 8
        for (int j = 0; j < 128; j++) tot += red[threadIdx.x*128 + j];
        g_part[bn*32 + threadIdx.x] = tot;
    }
}

// Reduce 1024 block partials -> BN scale/shift per channel (deterministic)
__global__ void k_stats(const float* __restrict__ gamma, const float* __restrict__ beta) {
    __shared__ float part[256];
    __shared__ float ss[32];
    int t = threadIdx.x;             // 256
    int col = t & 31, seg = t >> 5;  // 8 segments of 128 blocks
    float a = 0.f;
    for (int j = seg*128; j < seg*128 + 128; j++) a += g_part[j*32 + col];
    part[t] = a;
    __syncthreads();
    if (t < 32) {
        float tot = 0.f;
        #pragma unroll
        for (int sg = 0; sg < 8; sg++) tot += part[sg*32 + t];
        ss[t] = tot;
    }
    __syncthreads();
    if (t < CH_) {
        float mean = ss[t] / (float)CNT_;
        float var  = ss[t+16] / (float)CNT_ - mean*mean;
        float sc = gamma[t] * rsqrtf(var + 1e-5f);
        g_scale[t] = sc;
        g_shift[t] = beta[t] - mean*sc;
    }
}

// BN + ReLU + W2 epilogue; writes out[b][o][t*N+n] coalesced (n fastest).
__global__ void k_out(const float* __restrict__ W2, const float* __restrict__ b2,
                      float* __restrict__ out) {
    __shared__ float sW2[CH_*CH_], sb2[CH_], ssc[CH_], ssh[CH_];
    if (threadIdx.x < CH_*CH_) sW2[threadIdx.x] = W2[threadIdx.x];
    if (threadIdx.x < CH_) {
        sb2[threadIdx.x] = b2[threadIdx.x];
        ssc[threadIdx.x] = g_scale[threadIdx.x];
        ssh[threadIdx.x] = g_shift[threadIdx.x];
    }
    __syncthreads();
    int tid = blockIdx.x*blockDim.x + threadIdx.x;   // 409600
    int b = tid / L_;
    int l = tid - b*L_;
    int t = l >> 9, n = l & (N_-1);
    const float4* hp = (const float4*)(g_h + (((size_t)(b*N_+n))*FT_ + t)*CH_);
    float4 a0 = hp[0], a1 = hp[1], a2 = hp[2], a3 = hp[3];
    float hr[CH_];
    hr[0]=a0.x; hr[1]=a0.y; hr[2]=a0.z; hr[3]=a0.w;
    hr[4]=a1.x; hr[5]=a1.y; hr[6]=a1.z; hr[7]=a1.w;
    hr[8]=a2.x; hr[9]=a2.y; hr[10]=a2.z; hr[11]=a2.w;
    hr[12]=a3.x; hr[13]=a3.y; hr[14]=a3.z; hr[15]=a3.w;
    #pragma unroll
    for (int o = 0; o < CH_; o++) hr[o] = fmaxf(ssc[o]*hr[o] + ssh[o], 0.f);
    #pragma unroll
    for (int o2 = 0; o2 < CH_; o2++) {
        float acc = sb2[o2];
        #pragma unroll
        for (int o = 0; o < CH_; o++) acc += sW2[o2*16+o] * hr[o];
        out[((size_t)(b*CH_+o2))*L_ + l] = acc;
    }
}

extern "C" void kernel_launch(void* const* d_in, const int* in_sizes, int n_in,
                              void* d_out, int out_size) {
    const float* x     = (const float*)d_in[0];
    const int*   coord = (const int*)  d_in[1];
    const float* Wf    = (const float*)d_in[2];
    const float* bf    = (const float*)d_in[3];
    const float* Wr    = (const float*)d_in[4];
    const float* br    = (const float*)d_in[5];
    const float* W1    = (const float*)d_in[6];
    const float* b1    = (const float*)d_in[7];
    const float* gamma = (const float*)d_in[8];
    const float* beta  = (const float*)d_in[9];
    const float* W2    = (const float*)d_in[10];
    const float* b2    = (const float*)d_in[11];
    float* out = (float*)d_out;

    k_init  <<<1,     512>>>(W1, Wf, b1, bf);
    k_r     <<<2048,  256>>>(x, Wr, br);        // streams x, warms L2 for the gather
    k_gather<<<1024,  128>>>(x, coord);         // scattered reads likely L2 hits
    k_r2    <<<12800, 256>>>(out);
    k_stats <<<1,     256>>>(gamma, beta);
    k_out   <<<1600,  256>>>(W2, b2, out);
}